// round 1
// baseline (speedup 1.0000x reference)
#include <cuda_runtime.h>

// Problem constants (fixed by the reference)
#define B_ROWS 4096
#define NDOM 8
#define D0 1024   // d_in
#define D1 1024
#define D2 512
#define D3 256

// ---------------- device scratch (no allocations allowed) ----------------
__device__ int   g_perm[B_ROWS];          // rows sorted by domain
__device__ int   g_off[NDOM + 1];         // domain segment offsets
__device__ float g_weff0[NDOM * D0 * D1]; // fused sk0*dk0  (32 MB)
__device__ float g_weff1[NDOM * D1 * D2]; // 16 MB
__device__ float g_weff2[NDOM * D2 * D3]; //  4 MB
__device__ float g_h1[B_ROWS * D1];       // layer-0 activations (sorted order)
__device__ float g_h2[B_ROWS * D2];       // layer-1 activations (sorted order)

// ---------------- build per-domain permutation ----------------
__global__ void build_perm(const int* __restrict__ ind) {
    __shared__ int cnt[NDOM];
    __shared__ int cur[NDOM];
    int t = threadIdx.x;
    if (t < NDOM) cnt[t] = 0;
    __syncthreads();
    for (int i = t; i < B_ROWS; i += blockDim.x)
        atomicAdd(&cnt[ind[i]], 1);
    __syncthreads();
    if (t == 0) {
        int s = 0;
        for (int d = 0; d < NDOM; d++) {
            g_off[d] = s;
            cur[d]   = s;
            s += cnt[d];
        }
        g_off[NDOM] = s;
    }
    __syncthreads();
    for (int i = t; i < B_ROWS; i += blockDim.x) {
        int d = ind[i];
        int p = atomicAdd(&cur[d], 1);
        g_perm[p] = i;
    }
}

// ---------------- fuse shared * domain weights ----------------
// weff[d][k][n] = sk[k][n] * dk[d][k][n]
template <int LAYER>
__global__ void fuse_weights(const float* __restrict__ sk,
                             const float* __restrict__ dk,
                             int KN) {
    float* weff = (LAYER == 0) ? g_weff0 : (LAYER == 1) ? g_weff1 : g_weff2;
    int i = blockIdx.x * blockDim.x + threadIdx.x;   // one float4 per thread
    int total4 = (NDOM * KN) >> 2;
    if (i < total4) {
        int idx = i << 2;
        int kn  = idx % KN;                           // KN is a multiple of 4
        float4 s = *(const float4*)(sk + kn);
        float4 w = *(const float4*)(dk + idx);
        w.x *= s.x; w.y *= s.y; w.z *= s.z; w.w *= s.w;
        *(float4*)(weff + idx) = w;
    }
}

// ---------------- grouped GEMM (per-domain segments) ----------------
// C[m][n] = relu( sum_k A[m][k] * Weff[d][k][n] + sb[n] + db[d][n] )
// LAYER 0: A = x gathered via g_perm, C = g_h1
// LAYER 1: A = g_h1 (direct),        C = g_h2
// LAYER 2: A = g_h2 (direct),        C = d_out scattered via g_perm
template <int LAYER>
__global__ __launch_bounds__(256)
void gemm_star(const float* __restrict__ xin,
               const float* __restrict__ sb,
               const float* __restrict__ db,
               float* __restrict__ cout_,
               int K, int N) {
    constexpr int TM = 64, TN = 64, TK = 32;

    const int d   = blockIdx.z;
    const int off = g_off[d];
    const int len = g_off[d + 1] - off;
    const int m0  = blockIdx.y * TM;
    if (m0 >= len) return;                   // uniform across block
    const int n0  = blockIdx.x * TN;

    const float* A = (LAYER == 0) ? xin   : (LAYER == 1) ? g_h1   : g_h2;
    const float* W = (LAYER == 0) ? g_weff0 : (LAYER == 1) ? g_weff1 : g_weff2;
    float*       C = (LAYER == 0) ? g_h1  : (LAYER == 1) ? g_h2   : cout_;

    __shared__ float As[TM][TK + 1];   // +1 pad: conflict-free column reads
    __shared__ float Ws[TK][TN];
    __shared__ int   rowIdx[TM];

    const int tid = threadIdx.x;       // 256 threads
    if (tid < TM) {
        int r = m0 + tid;
        int row = -1;
        if (r < len) row = (LAYER == 0) ? g_perm[off + r] : (off + r);
        rowIdx[tid] = row;
    }
    __syncthreads();

    float acc[4][4];
#pragma unroll
    for (int i = 0; i < 4; i++)
#pragma unroll
        for (int j = 0; j < 4; j++) acc[i][j] = 0.f;

    const int tx = tid & 15;           // 16 col groups of 4
    const int ty = tid >> 4;           // 16 row groups of 4
    const float* Wd = W + (size_t)d * K * N;

    for (int k0 = 0; k0 < K; k0 += TK) {
        // Load A tile: 64x32 floats = 512 float4, 2 per thread
#pragma unroll
        for (int i = 0; i < 2; i++) {
            int li = tid + i * 256;
            int m  = li >> 3;
            int kq = (li & 7) << 2;
            float4 v = make_float4(0.f, 0.f, 0.f, 0.f);
            int row = rowIdx[m];
            if (row >= 0)
                v = *(const float4*)(A + (size_t)row * K + k0 + kq);
            As[m][kq + 0] = v.x;
            As[m][kq + 1] = v.y;
            As[m][kq + 2] = v.z;
            As[m][kq + 3] = v.w;
        }
        // Load W tile: 32x64 floats = 512 float4, 2 per thread
#pragma unroll
        for (int i = 0; i < 2; i++) {
            int li = tid + i * 256;
            int kk = li >> 4;
            int nq = (li & 15) << 2;
            float4 v = *(const float4*)(Wd + (size_t)(k0 + kk) * N + n0 + nq);
            *(float4*)(&Ws[kk][nq]) = v;
        }
        __syncthreads();

#pragma unroll
        for (int kk = 0; kk < TK; kk++) {
            float4 bv = *(float4*)(&Ws[kk][tx << 2]);
            float a0 = As[(ty << 2) + 0][kk];
            float a1 = As[(ty << 2) + 1][kk];
            float a2 = As[(ty << 2) + 2][kk];
            float a3 = As[(ty << 2) + 3][kk];
            acc[0][0] += a0 * bv.x; acc[0][1] += a0 * bv.y;
            acc[0][2] += a0 * bv.z; acc[0][3] += a0 * bv.w;
            acc[1][0] += a1 * bv.x; acc[1][1] += a1 * bv.y;
            acc[1][2] += a1 * bv.z; acc[1][3] += a1 * bv.w;
            acc[2][0] += a2 * bv.x; acc[2][1] += a2 * bv.y;
            acc[2][2] += a2 * bv.z; acc[2][3] += a2 * bv.w;
            acc[3][0] += a3 * bv.x; acc[3][1] += a3 * bv.y;
            acc[3][2] += a3 * bv.z; acc[3][3] += a3 * bv.w;
        }
        __syncthreads();
    }

    // Epilogue: bias + relu, store (scatter for final layer)
    const int nbase = n0 + (tx << 2);
    float4 bs = *(const float4*)(sb + nbase);
    float4 bd = *(const float4*)(db + (size_t)d * N + nbase);
    const float b0 = bs.x + bd.x, b1 = bs.y + bd.y;
    const float b2 = bs.z + bd.z, b3 = bs.w + bd.w;

#pragma unroll
    for (int i = 0; i < 4; i++) {
        int r = m0 + (ty << 2) + i;
        if (r < len) {
            int orow = (LAYER == 2) ? g_perm[off + r] : (off + r);
            float4 o;
            o.x = fmaxf(acc[i][0] + b0, 0.f);
            o.y = fmaxf(acc[i][1] + b1, 0.f);
            o.z = fmaxf(acc[i][2] + b2, 0.f);
            o.w = fmaxf(acc[i][3] + b3, 0.f);
            *(float4*)(C + (size_t)orow * N + nbase) = o;
        }
    }
}

// ---------------- launch ----------------
extern "C" void kernel_launch(void* const* d_in, const int* in_sizes, int n_in,
                              void* d_out, int out_size) {
    const float* x   = (const float*)d_in[0];
    const int*   ind = (const int*)  d_in[1];
    const float* sk0 = (const float*)d_in[2];
    const float* sb0 = (const float*)d_in[3];
    const float* dk0 = (const float*)d_in[4];
    const float* db0 = (const float*)d_in[5];
    const float* sk1 = (const float*)d_in[6];
    const float* sb1 = (const float*)d_in[7];
    const float* dk1 = (const float*)d_in[8];
    const float* db1 = (const float*)d_in[9];
    const float* sk2 = (const float*)d_in[10];
    const float* sb2 = (const float*)d_in[11];
    const float* dk2 = (const float*)d_in[12];
    const float* db2 = (const float*)d_in[13];
    float* out = (float*)d_out;

    // 1) permutation by domain
    build_perm<<<1, 256>>>(ind);

    // 2) fused weights (independent of perm; stream-ordered anyway)
    {
        int kn0 = D0 * D1, t0 = (NDOM * kn0) >> 2;
        fuse_weights<0><<<(t0 + 255) / 256, 256>>>(sk0, dk0, kn0);
        int kn1 = D1 * D2, t1 = (NDOM * kn1) >> 2;
        fuse_weights<1><<<(t1 + 255) / 256, 256>>>(sk1, dk1, kn1);
        int kn2 = D2 * D3, t2 = (NDOM * kn2) >> 2;
        fuse_weights<2><<<(t2 + 255) / 256, 256>>>(sk2, dk2, kn2);
    }

    // 3) three grouped GEMM layers
    {
        dim3 g0(D1 / 64, B_ROWS / 64, NDOM);
        gemm_star<0><<<g0, 256>>>(x, sb0, db0, nullptr, D0, D1);
        dim3 g1(D2 / 64, B_ROWS / 64, NDOM);
        gemm_star<1><<<g1, 256>>>(nullptr, sb1, db1, nullptr, D1, D2);
        dim3 g2(D3 / 64, B_ROWS / 64, NDOM);
        gemm_star<2><<<g2, 256>>>(nullptr, sb2, db2, out, D2, D3);
    }
}

// round 3
// speedup vs baseline: 1.4951x; 1.4951x over previous
#include <cuda_runtime.h>
#include <cstdint>

// Problem constants
#define B_ROWS 4096
#define NDOM 8
#define D0 1024
#define D1 1024
#define D2 512
#define D3 256
#define MAXTILES 40

// ---------------- device scratch ----------------
__device__ int   g_perm[B_ROWS];
__device__ int   g_off[NDOM + 1];
__device__ int   g_tile_d[MAXTILES];
__device__ int   g_tile_m[MAXTILES];
__device__ int   g_ntiles;
// fused, transposed, tf32-split weights: [d][n][k]
__device__ float g_wb0[NDOM * D1 * D0];
__device__ float g_ws0[NDOM * D1 * D0];
__device__ float g_wb1[NDOM * D2 * D1];
__device__ float g_ws1[NDOM * D2 * D1];
__device__ float g_wb2[NDOM * D3 * D2];
__device__ float g_ws2[NDOM * D3 * D2];
__device__ float g_h1[B_ROWS * D1];
__device__ float g_h2[B_ROWS * D2];

__device__ __forceinline__ float tf32r(float x) {
    uint32_t u;
    asm("cvt.rna.tf32.f32 %0, %1;" : "=r"(u) : "f"(x));
    return __uint_as_float(u);
}

#define MMA_TF32(d, a, b)                                                     \
    asm volatile(                                                             \
        "mma.sync.aligned.m16n8k8.row.col.f32.tf32.tf32.f32 "                 \
        "{%0,%1,%2,%3}, {%4,%5,%6,%7}, {%8,%9}, {%0,%1,%2,%3};"               \
        : "+f"((d)[0]), "+f"((d)[1]), "+f"((d)[2]), "+f"((d)[3])              \
        : "r"((a)[0]), "r"((a)[1]), "r"((a)[2]), "r"((a)[3]),                 \
          "r"((b)[0]), "r"((b)[1]))

// ---------------- permutation + tile list ----------------
__global__ void build_perm(const int* __restrict__ ind) {
    __shared__ int cnt[NDOM];
    __shared__ int cur[NDOM];
    int t = threadIdx.x;
    if (t < NDOM) cnt[t] = 0;
    __syncthreads();
    for (int i = t; i < B_ROWS; i += blockDim.x) atomicAdd(&cnt[ind[i]], 1);
    __syncthreads();
    if (t == 0) {
        int s = 0;
        for (int d = 0; d < NDOM; d++) { g_off[d] = s; cur[d] = s; s += cnt[d]; }
        g_off[NDOM] = s;
        int nt = 0;
        for (int d = 0; d < NDOM; d++) {
            int len = g_off[d + 1] - g_off[d];
            for (int m0 = 0; m0 < len; m0 += 128) {
                g_tile_d[nt] = d; g_tile_m[nt] = m0; nt++;
            }
        }
        g_ntiles = nt;
    }
    __syncthreads();
    for (int i = t; i < B_ROWS; i += blockDim.x) {
        int d = ind[i];
        int p = atomicAdd(&cur[d], 1);
        g_perm[p] = i;
    }
}

// ---------------- fuse + transpose + tf32 split ----------------
// wb/ws[d][n][k] = split( sk[k][n] * dk[d][k][n] )
template <int LAYER>
__global__ void fuse_split(const float* __restrict__ sk, const float* __restrict__ dk) {
    constexpr int Kt = (LAYER == 0) ? D0 : (LAYER == 1) ? D1 : D2;
    constexpr int Nt = (LAYER == 0) ? D1 : (LAYER == 1) ? D2 : D3;
    float* wb = (LAYER == 0) ? g_wb0 : (LAYER == 1) ? g_wb1 : g_wb2;
    float* ws = (LAYER == 0) ? g_ws0 : (LAYER == 1) ? g_ws1 : g_ws2;
    __shared__ float t[32][33];
    const int k0 = blockIdx.x * 32, n0 = blockIdx.y * 32, d = blockIdx.z;
    const int tx = threadIdx.x, ty = threadIdx.y;   // 32 x 8
#pragma unroll
    for (int i = 0; i < 4; i++) {
        int kl = ty + i * 8;
        t[kl][tx] = sk[(size_t)(k0 + kl) * Nt + n0 + tx] *
                    dk[((size_t)d * Kt + k0 + kl) * Nt + n0 + tx];
    }
    __syncthreads();
#pragma unroll
    for (int i = 0; i < 4; i++) {
        int nl = ty + i * 8;
        float v = t[tx][nl];
        float b = tf32r(v);
        float s = tf32r(v - b);
        size_t o = ((size_t)d * Nt + n0 + nl) * Kt + k0 + tx;
        wb[o] = b; ws[o] = s;
    }
}

// ---------------- 3xTF32 mma.sync grouped GEMM ----------------
// Block tile M=128,N=128, K-chunk 32. 8 warps (2 M x 4 N), warp tile 64x32.
// smem layout (floats, row stride 36 for conflict-free frags):
//   Ab @0, As @128*36, Bb @2*128*36, Bs @3*128*36
//   rowIdx (int[128]) @ 4*128*36 floats; bias (float[128]) after.
#define TSTRIDE 36
#define TFLOATS (128 * TSTRIDE)
#define SM_ROWIDX (4 * TFLOATS)
#define SM_BIAS   (SM_ROWIDX + 128)
#define GEMM_SMEM ((SM_BIAS + 128) * 4)

template <int LAYER>
__global__ __launch_bounds__(256, 1)
void gemm_mma(const float* __restrict__ xin, const float* __restrict__ sb,
              const float* __restrict__ db, float* __restrict__ outp) {
    constexpr int K = (LAYER == 0) ? D0 : (LAYER == 1) ? D1 : D2;
    constexpr int N = (LAYER == 0) ? D1 : (LAYER == 1) ? D2 : D3;
    constexpr int NCH = K / 32;

    const int tyb = blockIdx.y;
    if (tyb >= g_ntiles) return;
    const int d   = g_tile_d[tyb];
    const int m0  = g_tile_m[tyb];
    const int off = g_off[d];
    const int len = g_off[d + 1] - off;
    const int n0  = blockIdx.x * 128;

    extern __shared__ float smf[];
    float* Ab = smf;
    float* As = smf + TFLOATS;
    float* Bb = smf + 2 * TFLOATS;
    float* Bs = smf + 3 * TFLOATS;
    int*   rowIdx = (int*)(smf + SM_ROWIDX);
    float* biasS  = smf + SM_BIAS;

    const int tid  = threadIdx.x;
    const int lane = tid & 31;
    const int w    = tid >> 5;
    const int mw   = w >> 2;        // 0..1
    const int nw   = w & 3;         // 0..3
    const int grp  = lane >> 2;     // 0..7
    const int tig  = lane & 3;      // 0..3

    if (tid < 128) {
        int r = m0 + tid;
        int row = -1;
        if (r < len) row = (LAYER == 0) ? g_perm[off + r] : (off + r);
        rowIdx[tid] = row;
    }
    if (tid >= 128 && tid < 160) {
        int q = tid - 128;
        float4 a = *(const float4*)(sb + n0 + q * 4);
        float4 b = *(const float4*)(db + (size_t)d * N + n0 + q * 4);
        a.x += b.x; a.y += b.y; a.z += b.z; a.w += b.w;
        *(float4*)(biasS + q * 4) = a;
    }
    __syncthreads();

    const float* Ap = (LAYER == 0) ? xin : (LAYER == 1) ? g_h1 : g_h2;
    const float* Wb = (LAYER == 0) ? g_wb0 : (LAYER == 1) ? g_wb1 : g_wb2;
    const float* Ws = (LAYER == 0) ? g_ws0 : (LAYER == 1) ? g_ws1 : g_ws2;
    float*       Cp = (LAYER == 0) ? g_h1 : (LAYER == 1) ? g_h2 : outp;
    const float* wbp0 = Wb + ((size_t)d * N + n0) * K;
    const float* wsp0 = Ws + ((size_t)d * N + n0) * K;

    float acc[4][4][4];
#pragma unroll
    for (int i = 0; i < 4; i++)
#pragma unroll
        for (int j = 0; j < 4; j++)
#pragma unroll
            for (int q = 0; q < 4; q++) acc[i][j][q] = 0.f;

    // per-thread load coordinates (4 float4 per operand tile)
    const int ldRow = tid >> 3;       // base row (0..31) + 32*i
    const int ldQ   = (tid & 7) * 4;  // col within 32

    float4 avA[4], avBb[4], avBs[4];

    // prefetch chunk 0
    {
        const int k0 = 0;
#pragma unroll
        for (int i = 0; i < 4; i++) {
            int row = ldRow + 32 * i;
            int rr = rowIdx[row];
            avA[i] = (rr >= 0) ? *(const float4*)(Ap + (size_t)rr * K + k0 + ldQ)
                               : make_float4(0.f, 0.f, 0.f, 0.f);
            avBb[i] = *(const float4*)(wbp0 + (size_t)row * K + k0 + ldQ);
            avBs[i] = *(const float4*)(wsp0 + (size_t)row * K + k0 + ldQ);
        }
    }

    for (int c = 0; c < NCH; c++) {
        // store regs -> smem (split A on the fly)
#pragma unroll
        for (int i = 0; i < 4; i++) {
            int row = ldRow + 32 * i;
            int o = row * TSTRIDE + ldQ;
            float4 v = avA[i];
            float4 vb, vs;
            vb.x = tf32r(v.x); vs.x = tf32r(v.x - vb.x);
            vb.y = tf32r(v.y); vs.y = tf32r(v.y - vb.y);
            vb.z = tf32r(v.z); vs.z = tf32r(v.z - vb.z);
            vb.w = tf32r(v.w); vs.w = tf32r(v.w - vb.w);
            *(float4*)(Ab + o) = vb;
            *(float4*)(As + o) = vs;
            *(float4*)(Bb + o) = avBb[i];
            *(float4*)(Bs + o) = avBs[i];
        }
        __syncthreads();

        // prefetch next chunk (LDG overlaps MMA below)
        if (c + 1 < NCH) {
            const int k0 = (c + 1) * 32;
#pragma unroll
            for (int i = 0; i < 4; i++) {
                int row = ldRow + 32 * i;
                int rr = rowIdx[row];
                avA[i] = (rr >= 0) ? *(const float4*)(Ap + (size_t)rr * K + k0 + ldQ)
                                   : make_float4(0.f, 0.f, 0.f, 0.f);
                avBb[i] = *(const float4*)(wbp0 + (size_t)row * K + k0 + ldQ);
                avBs[i] = *(const float4*)(wsp0 + (size_t)row * K + k0 + ldQ);
            }
        }

#pragma unroll
        for (int ks = 0; ks < 4; ks++) {
            const int kc = ks * 8 + tig;
            uint32_t fab[4][4], fas[4][4];
#pragma unroll
            for (int mt = 0; mt < 4; mt++) {
                int r0 = mw * 64 + mt * 16 + grp;
                fab[mt][0] = __float_as_uint(Ab[r0 * TSTRIDE + kc]);
                fab[mt][1] = __float_as_uint(Ab[(r0 + 8) * TSTRIDE + kc]);
                fab[mt][2] = __float_as_uint(Ab[r0 * TSTRIDE + kc + 4]);
                fab[mt][3] = __float_as_uint(Ab[(r0 + 8) * TSTRIDE + kc + 4]);
                fas[mt][0] = __float_as_uint(As[r0 * TSTRIDE + kc]);
                fas[mt][1] = __float_as_uint(As[(r0 + 8) * TSTRIDE + kc]);
                fas[mt][2] = __float_as_uint(As[r0 * TSTRIDE + kc + 4]);
                fas[mt][3] = __float_as_uint(As[(r0 + 8) * TSTRIDE + kc + 4]);
            }
            uint32_t fbb[4][2], fbs[4][2];
#pragma unroll
            for (int nt = 0; nt < 4; nt++) {
                int nr = nw * 32 + nt * 8 + grp;
                fbb[nt][0] = __float_as_uint(Bb[nr * TSTRIDE + kc]);
                fbb[nt][1] = __float_as_uint(Bb[nr * TSTRIDE + kc + 4]);
                fbs[nt][0] = __float_as_uint(Bs[nr * TSTRIDE + kc]);
                fbs[nt][1] = __float_as_uint(Bs[nr * TSTRIDE + kc + 4]);
            }
#pragma unroll
            for (int mt = 0; mt < 4; mt++)
#pragma unroll
                for (int nt = 0; nt < 4; nt++) {
                    MMA_TF32(acc[mt][nt], fab[mt], fbb[nt]);
                    MMA_TF32(acc[mt][nt], fab[mt], fbs[nt]);
                    MMA_TF32(acc[mt][nt], fas[mt], fbb[nt]);
                }
        }
        __syncthreads();
    }

    // ---------------- epilogue: bias + relu + (scatter) store ----------------
#pragma unroll
    for (int mt = 0; mt < 4; mt++) {
#pragma unroll
        for (int half = 0; half < 2; half++) {
            int mrow = mw * 64 + mt * 16 + grp + half * 8;
            int r = m0 + mrow;
            if (r < len) {
                int orow = (LAYER == 2) ? g_perm[off + r] : (off + r);
                float* crow = Cp + (size_t)orow * N + n0;
#pragma unroll
                for (int nt = 0; nt < 4; nt++) {
                    int col = nw * 32 + nt * 8 + 2 * tig;
                    float2 o;
                    o.x = fmaxf(acc[mt][nt][half * 2 + 0] + biasS[col], 0.f);
                    o.y = fmaxf(acc[mt][nt][half * 2 + 1] + biasS[col + 1], 0.f);
                    *(float2*)(crow + col) = o;
                }
            }
        }
    }
}

// ---------------- launch ----------------
extern "C" void kernel_launch(void* const* d_in, const int* in_sizes, int n_in,
                              void* d_out, int out_size) {
    const float* x   = (const float*)d_in[0];
    const int*   ind = (const int*)  d_in[1];
    const float* sk0 = (const float*)d_in[2];
    const float* sb0 = (const float*)d_in[3];
    const float* dk0 = (const float*)d_in[4];
    const float* db0 = (const float*)d_in[5];
    const float* sk1 = (const float*)d_in[6];
    const float* sb1 = (const float*)d_in[7];
    const float* dk1 = (const float*)d_in[8];
    const float* db1 = (const float*)d_in[9];
    const float* sk2 = (const float*)d_in[10];
    const float* sb2 = (const float*)d_in[11];
    const float* dk2 = (const float*)d_in[12];
    const float* db2 = (const float*)d_in[13];
    float* out = (float*)d_out;

    cudaFuncSetAttribute(gemm_mma<0>, cudaFuncAttributeMaxDynamicSharedMemorySize, GEMM_SMEM);
    cudaFuncSetAttribute(gemm_mma<1>, cudaFuncAttributeMaxDynamicSharedMemorySize, GEMM_SMEM);
    cudaFuncSetAttribute(gemm_mma<2>, cudaFuncAttributeMaxDynamicSharedMemorySize, GEMM_SMEM);

    build_perm<<<1, 256>>>(ind);

    fuse_split<0><<<dim3(D0 / 32, D1 / 32, NDOM), dim3(32, 8)>>>(sk0, dk0);
    fuse_split<1><<<dim3(D1 / 32, D2 / 32, NDOM), dim3(32, 8)>>>(sk1, dk1);
    fuse_split<2><<<dim3(D2 / 32, D3 / 32, NDOM), dim3(32, 8)>>>(sk2, dk2);

    gemm_mma<0><<<dim3(D1 / 128, MAXTILES), 256, GEMM_SMEM>>>(x, sb0, db0, nullptr);
    gemm_mma<1><<<dim3(D2 / 128, MAXTILES), 256, GEMM_SMEM>>>(nullptr, sb1, db1, nullptr);
    gemm_mma<2><<<dim3(D3 / 128, MAXTILES), 256, GEMM_SMEM>>>(nullptr, sb2, db2, out);
}

// round 4
// speedup vs baseline: 1.6564x; 1.1079x over previous
#include <cuda_runtime.h>
#include <cstdint>

// Problem constants
#define B_ROWS 4096
#define NDOM 8
#define D0 1024
#define D1 1024
#define D2 512
#define D3 256
#define MAXTILES 40

// ---------------- device scratch ----------------
__device__ int   g_perm[B_ROWS];
__device__ int   g_off[NDOM + 1];
__device__ int   g_tile_d[MAXTILES];
__device__ int   g_tile_m[MAXTILES];
__device__ int   g_ntiles;
__device__ float g_h1[B_ROWS * D1];
__device__ float g_h2[B_ROWS * D2];

__device__ __forceinline__ float tf32r(float x) {
    uint32_t u;
    asm("cvt.rna.tf32.f32 %0, %1;" : "=r"(u) : "f"(x));
    return __uint_as_float(u);
}

#define MMA_TF32(d, a0, a1, a2, a3, b0, b1)                                   \
    asm volatile(                                                             \
        "mma.sync.aligned.m16n8k8.row.col.f32.tf32.tf32.f32 "                 \
        "{%0,%1,%2,%3}, {%4,%5,%6,%7}, {%8,%9}, {%0,%1,%2,%3};"               \
        : "+f"((d)[0]), "+f"((d)[1]), "+f"((d)[2]), "+f"((d)[3])              \
        : "r"(a0), "r"(a1), "r"(a2), "r"(a3), "r"(b0), "r"(b1))

// ---------------- permutation + tile list ----------------
__global__ void build_perm(const int* __restrict__ ind) {
    __shared__ int cnt[NDOM];
    __shared__ int cur[NDOM];
    int t = threadIdx.x;
    if (t < NDOM) cnt[t] = 0;
    __syncthreads();
    for (int i = t; i < B_ROWS; i += blockDim.x) atomicAdd(&cnt[ind[i]], 1);
    __syncthreads();
    if (t == 0) {
        int s = 0;
        for (int d = 0; d < NDOM; d++) { g_off[d] = s; cur[d] = s; s += cnt[d]; }
        g_off[NDOM] = s;
        int nt = 0;
        for (int d = 0; d < NDOM; d++) {
            int len = g_off[d + 1] - g_off[d];
            for (int m0 = 0; m0 < len; m0 += 128) {
                g_tile_d[nt] = d; g_tile_m[nt] = m0; nt++;
            }
        }
        g_ntiles = nt;
    }
    __syncthreads();
    for (int i = t; i < B_ROWS; i += blockDim.x) {
        int d = ind[i];
        int p = atomicAdd(&cur[d], 1);
        g_perm[p] = i;
    }
}

// ---------------- smem layout (floats) ----------------
// A fragments, MMA-permuted: [buf][split][mtile 0..7][lane 0..31][20]
//   per-lane: 4 ks * 4 regs at off ks*4+reg (16 used, stride 20 kills conflicts)
#define AF_SZ (2 * 2 * 8 * 32 * 20)       // 20480 floats
// B tiles: [buf][split][k 0..31][BPAD], value = weff(k, n0+n)
#define BPAD 132
#define B_SZ (2 * 2 * 32 * BPAD)          // 16896 floats
#define SM_B       AF_SZ
#define SM_ROWIDX  (AF_SZ + B_SZ)
#define SM_BIAS    (SM_ROWIDX + 128)
#define GEMM_SMEM  ((SM_BIAS + 128) * 4)  // ~150.5 KB

__device__ __forceinline__ int af_off(int buf, int split, int mtile) {
    return ((buf * 2 + split) * 8 + mtile) * 640;   // 32*20
}
__device__ __forceinline__ int b_off(int buf, int split) {
    return SM_B + (buf * 2 + split) * (32 * BPAD);
}

// ---------------- 3xTF32 mma.sync grouped GEMM, fused weight build ----------
// Block tile M=128, N=128, K-chunk 32, double-buffered. 8 warps (2M x 4N).
template <int LAYER>
__global__ __launch_bounds__(256, 1)
void gemm_mma(const float* __restrict__ xin, const float* __restrict__ sk,
              const float* __restrict__ dkk, const float* __restrict__ sb,
              const float* __restrict__ db, float* __restrict__ outp) {
    constexpr int K = (LAYER == 0) ? D0 : (LAYER == 1) ? D1 : D2;
    constexpr int N = (LAYER == 0) ? D1 : (LAYER == 1) ? D2 : D3;
    constexpr int NCH = K / 32;

    const int tyb = blockIdx.y;
    if (tyb >= g_ntiles) return;
    const int d   = g_tile_d[tyb];
    const int m0  = g_tile_m[tyb];
    const int off = g_off[d];
    const int len = g_off[d + 1] - off;
    const int n0  = blockIdx.x * 128;

    extern __shared__ float smf[];
    int*   rowIdx = (int*)(smf + SM_ROWIDX);
    float* biasS  = smf + SM_BIAS;

    const int tid  = threadIdx.x;
    const int lane = tid & 31;
    const int w    = tid >> 5;
    const int mw   = w >> 2;
    const int nw   = w & 3;
    const int grp  = lane >> 2;
    const int tig  = lane & 3;

    if (tid < 128) {
        int r = m0 + tid;
        int row = -1;
        if (r < len) row = (LAYER == 0) ? g_perm[off + r] : (off + r);
        rowIdx[tid] = row;
    }
    if (tid >= 128 && tid < 160) {
        int q = tid - 128;
        float4 a = *(const float4*)(sb + n0 + q * 4);
        float4 b = *(const float4*)(db + (size_t)d * N + n0 + q * 4);
        a.x += b.x; a.y += b.y; a.z += b.z; a.w += b.w;
        *(float4*)(biasS + q * 4) = a;
    }
    __syncthreads();

    const float* Ap  = (LAYER == 0) ? xin : (LAYER == 1) ? g_h1 : g_h2;
    float*       Cp  = (LAYER == 0) ? g_h1 : (LAYER == 1) ? g_h2 : outp;
    const float* dkd = dkk + (size_t)d * K * N;

    float acc[4][4][4];
#pragma unroll
    for (int i = 0; i < 4; i++)
#pragma unroll
        for (int j = 0; j < 4; j++)
#pragma unroll
            for (int q = 0; q < 4; q++) acc[i][j][q] = 0.f;

    // loader coords: A rows ldr+32i col fq*4..; B row k=ldr, float4 cols fq+8i
    const int ldr = tid >> 3;
    const int fq  = tid & 7;
    int rws[4];
#pragma unroll
    for (int i = 0; i < 4; i++) rws[i] = rowIdx[ldr + 32 * i];

    float4 avA[4], avS[4], avD[4];

#define LOADC(c)                                                              \
    {                                                                         \
        const int k0 = (c) * 32;                                              \
        _Pragma("unroll")                                                     \
        for (int i = 0; i < 4; i++) {                                         \
            int rr = rws[i];                                                  \
            avA[i] = (rr >= 0)                                                \
                ? *(const float4*)(Ap + (size_t)rr * K + k0 + fq * 4)         \
                : make_float4(0.f, 0.f, 0.f, 0.f);                            \
        }                                                                     \
        _Pragma("unroll")                                                     \
        for (int i = 0; i < 4; i++) {                                         \
            int co = n0 + (fq + 8 * i) * 4;                                   \
            avS[i] = *(const float4*)(sk  + (size_t)(k0 + ldr) * N + co);     \
            avD[i] = *(const float4*)(dkd + (size_t)(k0 + ldr) * N + co);     \
        }                                                                     \
    }

#define STOREC(c)                                                             \
    {                                                                         \
        const int buf = (c) & 1;                                              \
        const int ks  = fq >> 1;                                              \
        const int kh2 = (fq & 1) * 2;                                         \
        _Pragma("unroll")                                                     \
        for (int i = 0; i < 4; i++) {                                         \
            int row = ldr + 32 * i;                                           \
            int mt  = row >> 4;                                               \
            int l0  = (row & 7) * 4;                                          \
            int ai  = ((row & 15) >= 8 ? 1 : 0) + kh2;                        \
            float* pb = smf + af_off(buf, 0, mt) + ks * 4 + ai;               \
            float* ps = smf + af_off(buf, 1, mt) + ks * 4 + ai;               \
            float4 v = avA[i];                                                \
            float bx = tf32r(v.x), by = tf32r(v.y);                           \
            float bz = tf32r(v.z), bw = tf32r(v.w);                           \
            pb[(l0 + 0) * 20] = bx; ps[(l0 + 0) * 20] = tf32r(v.x - bx);      \
            pb[(l0 + 1) * 20] = by; ps[(l0 + 1) * 20] = tf32r(v.y - by);      \
            pb[(l0 + 2) * 20] = bz; ps[(l0 + 2) * 20] = tf32r(v.z - bz);      \
            pb[(l0 + 3) * 20] = bw; ps[(l0 + 3) * 20] = tf32r(v.w - bw);      \
        }                                                                     \
        _Pragma("unroll")                                                     \
        for (int i = 0; i < 4; i++) {                                         \
            float4 s = avS[i], t = avD[i];                                    \
            float4 wv, wb, ws;                                                \
            wv.x = s.x * t.x; wv.y = s.y * t.y;                               \
            wv.z = s.z * t.z; wv.w = s.w * t.w;                               \
            wb.x = tf32r(wv.x); ws.x = tf32r(wv.x - wb.x);                    \
            wb.y = tf32r(wv.y); ws.y = tf32r(wv.y - wb.y);                    \
            wb.z = tf32r(wv.z); ws.z = tf32r(wv.z - wb.z);                    \
            wb.w = tf32r(wv.w); ws.w = tf32r(wv.w - wb.w);                    \
            int o = ldr * BPAD + (fq + 8 * i) * 4;                            \
            *(float4*)(smf + b_off(buf, 0) + o) = wb;                         \
            *(float4*)(smf + b_off(buf, 1) + o) = ws;                         \
        }                                                                     \
    }

    LOADC(0);
    STOREC(0);

    for (int c = 0; c < NCH; c++) {
        const int buf = c & 1;
        __syncthreads();
        if (c + 1 < NCH) LOADC(c + 1);

        const float* afb = smf + af_off(buf, 0, mw * 4) + lane * 20;
        const float* afs = smf + af_off(buf, 1, mw * 4) + lane * 20;
        const float* bpb = smf + b_off(buf, 0);
        const float* bps = smf + b_off(buf, 1);
#pragma unroll
        for (int ks = 0; ks < 4; ks++) {
            uint4 fab[4], fas[4];
#pragma unroll
            for (int mt = 0; mt < 4; mt++) {
                fab[mt] = *(const uint4*)(afb + mt * 640 + ks * 4);
                fas[mt] = *(const uint4*)(afs + mt * 640 + ks * 4);
            }
            const int kc = ks * 8 + tig;
#pragma unroll
            for (int nt = 0; nt < 4; nt++) {
                int ncol = nw * 32 + nt * 8 + grp;
                uint32_t bb0 = __float_as_uint(bpb[kc * BPAD + ncol]);
                uint32_t bb1 = __float_as_uint(bpb[(kc + 4) * BPAD + ncol]);
                uint32_t bs0 = __float_as_uint(bps[kc * BPAD + ncol]);
                uint32_t bs1 = __float_as_uint(bps[(kc + 4) * BPAD + ncol]);
#pragma unroll
                for (int mt = 0; mt < 4; mt++) {
                    MMA_TF32(acc[mt][nt], fab[mt].x, fab[mt].y, fab[mt].z, fab[mt].w, bb0, bb1);
                    MMA_TF32(acc[mt][nt], fab[mt].x, fab[mt].y, fab[mt].z, fab[mt].w, bs0, bs1);
                    MMA_TF32(acc[mt][nt], fas[mt].x, fas[mt].y, fas[mt].z, fas[mt].w, bb0, bb1);
                }
            }
        }
        if (c + 1 < NCH) STOREC(c + 1);
    }

    // ---------------- epilogue: bias + relu + (scatter) store ----------------
#pragma unroll
    for (int mt = 0; mt < 4; mt++) {
#pragma unroll
        for (int half = 0; half < 2; half++) {
            int mrow = mw * 64 + mt * 16 + grp + half * 8;
            int r = m0 + mrow;
            if (r < len) {
                int orow = (LAYER == 2) ? g_perm[off + r] : (off + r);
                float* crow = Cp + (size_t)orow * N + n0;
#pragma unroll
                for (int nt = 0; nt < 4; nt++) {
                    int col = nw * 32 + nt * 8 + 2 * tig;
                    float2 o;
                    o.x = fmaxf(acc[mt][nt][half * 2 + 0] + biasS[col], 0.f);
                    o.y = fmaxf(acc[mt][nt][half * 2 + 1] + biasS[col + 1], 0.f);
                    *(float2*)(crow + col) = o;
                }
            }
        }
    }
}

// ---------------- launch ----------------
extern "C" void kernel_launch(void* const* d_in, const int* in_sizes, int n_in,
                              void* d_out, int out_size) {
    const float* x   = (const float*)d_in[0];
    const int*   ind = (const int*)  d_in[1];
    const float* sk0 = (const float*)d_in[2];
    const float* sb0 = (const float*)d_in[3];
    const float* dk0 = (const float*)d_in[4];
    const float* db0 = (const float*)d_in[5];
    const float* sk1 = (const float*)d_in[6];
    const float* sb1 = (const float*)d_in[7];
    const float* dk1 = (const float*)d_in[8];
    const float* db1 = (const float*)d_in[9];
    const float* sk2 = (const float*)d_in[10];
    const float* sb2 = (const float*)d_in[11];
    const float* dk2 = (const float*)d_in[12];
    const float* db2 = (const float*)d_in[13];
    float* out = (float*)d_out;

    cudaFuncSetAttribute(gemm_mma<0>, cudaFuncAttributeMaxDynamicSharedMemorySize, GEMM_SMEM);
    cudaFuncSetAttribute(gemm_mma<1>, cudaFuncAttributeMaxDynamicSharedMemorySize, GEMM_SMEM);
    cudaFuncSetAttribute(gemm_mma<2>, cudaFuncAttributeMaxDynamicSharedMemorySize, GEMM_SMEM);

    build_perm<<<1, 256>>>(ind);

    gemm_mma<0><<<dim3(D1 / 128, MAXTILES), 256, GEMM_SMEM>>>(x, sk0, dk0, sb0, db0, nullptr);
    gemm_mma<1><<<dim3(D2 / 128, MAXTILES), 256, GEMM_SMEM>>>(nullptr, sk1, dk1, sb1, db1, nullptr);
    gemm_mma<2><<<dim3(D3 / 128, MAXTILES), 256, GEMM_SMEM>>>(nullptr, sk2, dk2, sb2, db2, out);
}